// round 9
// baseline (speedup 1.0000x reference)
#include <cuda_runtime.h>
#include <cuda_fp16.h>
#include <cstdint>

#define N_NODES    100000
#define EMB_DIM    128
#define BATCH      16384
#define NUM_SAMPLE 25

// fp16 shadow table: 100000 x 128 halfs = 25.6 MB (static device global)
__device__ __half g_emb_h[(size_t)N_NODES * EMB_DIM];

// ---------------- conversion: fp32 table -> fp16 shadow ----------------
__global__ __launch_bounds__(256) void convert_kernel(const float4* __restrict__ emb)
{
    const int n = N_NODES * EMB_DIM / 8;   // 1,600,000 uint4-of-halfs
    int i = blockIdx.x * blockDim.x + threadIdx.x;
    if (i >= n) return;

    float4 a = __ldg(&emb[2 * i]);
    float4 b = __ldg(&emb[2 * i + 1]);

    __half2 h0 = __float22half2_rn(make_float2(a.x, a.y));
    __half2 h1 = __float22half2_rn(make_float2(a.z, a.w));
    __half2 h2 = __float22half2_rn(make_float2(b.x, b.y));
    __half2 h3 = __float22half2_rn(make_float2(b.z, b.w));

    uint4 o;
    o.x = *reinterpret_cast<unsigned int*>(&h0);
    o.y = *reinterpret_cast<unsigned int*>(&h1);
    o.z = *reinterpret_cast<unsigned int*>(&h2);
    o.w = *reinterpret_cast<unsigned int*>(&h3);
    reinterpret_cast<uint4*>(g_emb_h)[i] = o;
}

// ---------------- gather-mean, half-warp per row, LDG.128 ----------------
// Warp owns rows {2w, 2w+1}. Lanes 0-15 -> row0, lanes 16-31 -> row1.
// Lane covers dims [sub*8, sub*8+8) via one uint4 (8 halfs) per sample.
#define GATHER_THREADS 128
#define GATHER_BLOCKS  (BATCH / 2 / (GATHER_THREADS / 32))   // 2048

__global__ __launch_bounds__(GATHER_THREADS) void gather_kernel(
    const int* __restrict__ neigh,   // [BATCH, NUM_SAMPLE] int32
    float4* __restrict__ out)        // [BATCH, 32] as float4
{
    const int warp_id = (blockIdx.x * GATHER_THREADS + threadIdx.x) >> 5;
    const int lane    = threadIdx.x & 31;
    const int sub     = lane & 15;       // position within half-warp
    const int half_hi = lane >> 4;       // 0 -> row0, 1 -> row1

    const int row0 = warp_id * 2;
    const int row1 = row0 + 1;

    // Lane l (<25) holds sample l's index for each row.
    const int* nb0 = neigh + row0 * NUM_SAMPLE;
    const int* nb1 = neigh + row1 * NUM_SAMPLE;
    int idx0 = (lane < NUM_SAMPLE) ? nb0[lane] : 0;
    int idx1 = (lane < NUM_SAMPLE) ? nb1[lane] : 0;

    const uint4* embh = reinterpret_cast<const uint4*>(g_emb_h);  // 16 uint4 per row

    float acc[8] = {0.f, 0.f, 0.f, 0.f, 0.f, 0.f, 0.f, 0.f};

    #pragma unroll
    for (int s = 0; s < NUM_SAMPLE; ++s) {
        int id0 = __shfl_sync(0xffffffffu, idx0, s);
        int id1 = __shfl_sync(0xffffffffu, idx1, s);
        int id  = half_hi ? id1 : id0;

        uint4 u = __ldg(&embh[(unsigned)id * 16u + sub]);

        __half2 h0 = *reinterpret_cast<__half2*>(&u.x);
        __half2 h1 = *reinterpret_cast<__half2*>(&u.y);
        __half2 h2 = *reinterpret_cast<__half2*>(&u.z);
        __half2 h3 = *reinterpret_cast<__half2*>(&u.w);
        float2 f0 = __half22float2(h0);
        float2 f1 = __half22float2(h1);
        float2 f2 = __half22float2(h2);
        float2 f3 = __half22float2(h3);

        acc[0] += f0.x; acc[1] += f0.y;
        acc[2] += f1.x; acc[3] += f1.y;
        acc[4] += f2.x; acc[5] += f2.y;
        acc[6] += f3.x; acc[7] += f3.y;
    }

    const float inv = 1.0f / (float)NUM_SAMPLE;
    #pragma unroll
    for (int k = 0; k < 8; ++k) acc[k] *= inv;

    // Lane covers dims [sub*8, sub*8+8) of its row -> two float4 stores.
    const int row = half_hi ? row1 : row0;
    float4* o = out + (unsigned)row * 32u + sub * 2;
    o[0] = make_float4(acc[0], acc[1], acc[2], acc[3]);
    o[1] = make_float4(acc[4], acc[5], acc[6], acc[7]);
}

extern "C" void kernel_launch(void* const* d_in, const int* in_sizes, int n_in,
                              void* d_out, int out_size)
{
    const float4* emb   = (const float4*)d_in[0];
    const int*    neigh = (const int*)d_in[1];
    float4*       out   = (float4*)d_out;

    // Pass 1: fp32 -> fp16 shadow (stream-ordered before gather).
    const int n_conv = N_NODES * EMB_DIM / 8;
    convert_kernel<<<(n_conv + 255) / 256, 256>>>(emb);

    // Pass 2: gather-mean from fp16 shadow.
    gather_kernel<<<GATHER_BLOCKS, GATHER_THREADS>>>(neigh, out);
}